// round 11
// baseline (speedup 1.0000x reference)
#include <cuda_runtime.h>
#include <stdint.h>

#define HH 2048
#define WW 2048
#define NPIX (HH * WW)

#define TW 32                    // tile width
#define TH 16                    // tile height
#define SW (TW + 2)              // 34 (halo)
#define SH (TH + 2)              // 18 (halo)
#define NSLOT (SW * SH)          // 612

#define NBX 64                   // tiles per row (bits in a mask word)
#define NBY 128                  // tile rows
#define NB  (NBX * NBY)          // 8192
#define GROUPS 4
#define STEP_GRID (NB / GROUPS)  // 2048 blocks, 1024 threads, 4 tile-groups

typedef unsigned long long ull;

__device__ float g_scratch[NPIX];
__device__ ull g_chmask[3][NBY];   // changed bits, 3-parity rotation
__device__ ull g_posmask[NBY];     // possible bits

// group barrier: named barrier (g+1), 256 threads
#define GBAR(g) asm volatile("bar.sync %0, 256;" :: "r"((g) + 1) : "memory")

// ---------------------------------------------------------------------------
// Threefry-2x32, 20 rounds — exact transcription of jax._src.prng
// ---------------------------------------------------------------------------
__host__ __device__ __forceinline__ uint32_t rotl32(uint32_t v, uint32_t r) {
#ifdef __CUDA_ARCH__
    return __funnelshift_l(v, v, r);
#else
    return (v << r) | (v >> (32u - r));
#endif
}

__host__ __device__ __forceinline__ void tf2x32(uint32_t k0, uint32_t k1,
                                                uint32_t x0, uint32_t x1,
                                                uint32_t& o0, uint32_t& o1) {
    uint32_t ks2 = k0 ^ k1 ^ 0x1BD11BDAu;
    x0 += k0; x1 += k1;
#define TF_R(r) { x0 += x1; x1 = rotl32(x1, r); x1 ^= x0; }
    TF_R(13u) TF_R(15u) TF_R(26u) TF_R(6u)
    x0 += k1;  x1 += ks2 + 1u;
    TF_R(17u) TF_R(29u) TF_R(16u) TF_R(24u)
    x0 += ks2; x1 += k0 + 2u;
    TF_R(13u) TF_R(15u) TF_R(26u) TF_R(6u)
    x0 += k0;  x1 += k1 + 3u;
    TF_R(17u) TF_R(29u) TF_R(16u) TF_R(24u)
    x0 += k1;  x1 += ks2 + 4u;
    TF_R(13u) TF_R(15u) TF_R(26u) TF_R(6u)
    x0 += ks2; x1 += k0 + 5u;
#undef TF_R
    o0 = x0; o1 = x1;
}

// Partitionable-mode random bits for flat index p: counter=(0,p); bits=o0^o1
__device__ __forceinline__ uint32_t pbits(uint32_t k0, uint32_t k1, uint32_t p) {
    uint32_t o0, o1;
    tf2x32(k0, k1, 0u, p, o0, o1);
    return o0 ^ o1;
}

__device__ __forceinline__ float bits_to_uniform(uint32_t bits) {
    return __fsub_rn(__uint_as_float((bits >> 9) | 0x3f800000u), 1.0f);
}

// ---------------------------------------------------------------------------
// x0 = seed * habitat * goodness  (+ reset masks)
// ---------------------------------------------------------------------------
__global__ void init_kernel(const float* __restrict__ seed,
                            const float* __restrict__ hab,
                            const float* __restrict__ good,
                            float* __restrict__ xout) {
    int idx = blockIdx.x * blockDim.x + threadIdx.x;
    if (idx < NPIX / 4) {
        const float4 s = ((const float4*)seed)[idx];
        const float4 h = ((const float4*)hab)[idx];
        const float4 g = ((const float4*)good)[idx];
        float4 o;
        o.x = __fmul_rn(__fmul_rn(s.x, h.x), g.x);
        o.y = __fmul_rn(__fmul_rn(s.y, h.y), g.y);
        o.z = __fmul_rn(__fmul_rn(s.z, h.z), g.z);
        o.w = __fmul_rn(__fmul_rn(s.w, h.w), g.w);
        ((float4*)xout)[idx] = o;
    }
    if (idx < NBY) {
        g_chmask[2][idx] = ~0ull;   // prev parity of iter 0 -> force all tiles
        g_chmask[0][idx] = 0ull;
        g_chmask[1][idx] = 0ull;
        g_posmask[idx]   = 0ull;
    }
}

// ---------------------------------------------------------------------------
// One spread step. 1024-thread block = 4 independent 256-thread groups,
// each owning one tile, synced by named barriers only (no serialization).
//   y1 = x * (0.9999 + 1e-4*u1); y2 = maxpool3x3(y1); y3 = y2*(u2>0.5);
//   y4 = y3*goodness; x' = max(y4*((y4-x) > 0.05), x)
// Skip hierarchy (exact: good<1, noise factor <= 1):
//   tile masks -> pretest M-x>0.05 (no good load) -> exact pos -> gated RNG.
// ---------------------------------------------------------------------------
__global__ __launch_bounds__(1024, 2)
void step_kernel(const float* __restrict__ xin, float* __restrict__ xout,
                 const float* __restrict__ good,
                 uint32_t k1a, uint32_t k1b, uint32_t k2a, uint32_t k2b,
                 int prev, int cur, int nxt) {
    __shared__ float xs[GROUPS][SH][SW];   // raw x (tile + halo)
    __shared__ float ys[GROUPS][SH][SW];   // noised x (maxpool operand)
    __shared__ unsigned s_rowpos[GROUPS][TH];
    __shared__ int s_red1[GROUPS], s_red2[GROUPS], s_red3[GROUPS];

    const int tid = threadIdx.x;
    const int g  = tid >> 8;               // group = tile index within block
    const int gt = tid & 255;
    const int tx = gt & 31;
    const int ty = gt >> 5;                // 0..7

    // zero the next-parity mask row (not read or written this launch)
    if (blockIdx.x < NBY && tid == 0) g_chmask[nxt][blockIdx.x] = 0ull;

    const int t  = blockIdx.x * GROUPS + g;
    const int by = t >> 6;
    const int bx = t & 63;

    // uniform-within-group mask loads (L2 broadcast across groups)
    ull nbm = g_chmask[prev][by];
    const ull chm = nbm;
    if (by > 0)       nbm |= g_chmask[prev][by - 1];
    if (by < NBY - 1) nbm |= g_chmask[prev][by + 1];
    const ull posw = g_posmask[by];

    const ull colm = (bx == 0) ? 3ull : (7ull << (bx - 1));
    const bool need = ((nbm & colm) != 0ull) || (((posw >> bx) & 1ull) != 0ull);
    if (!need) return;                      // group-uniform exit

    const int selfchg = (int)((chm >> bx) & 1ull);
    const int c0 = bx * TW, r0 = by * TH;

    if (gt == 0) { s_red1[g] = 0; s_red2[g] = 0; s_red3[g] = 0; }

    // ==== load tile: core via float4 (gt 0-127), halo ring (gt 128-227) ====
    if (gt < 128) {
        int row = gt >> 3, q = gt & 7;
        const float4 v = *(const float4*)&xin[(r0 + row) * WW + c0 + q * 4];
        float* dst = &xs[g][row + 1][1 + q * 4];
        dst[0] = v.x; dst[1] = v.y; dst[2] = v.z; dst[3] = v.w;
    } else {
        int h = gt - 128;
        if (h < 100) {
            int j, i;
            if (h < 34)      { j = 0;             i = h; }
            else if (h < 68) { j = SH - 1;        i = h - 34; }
            else if (h < 84) { j = 1 + (h - 68);  i = 0; }
            else             { j = 1 + (h - 84);  i = SW - 1; }
            int r = r0 - 1 + j, c = c0 - 1 + i;
            bool ok = (r >= 0) && (r < HH) && (c >= 0) && (c < WW);
            xs[g][j][i] = ok ? xin[r * WW + c] : 0.0f;
        }
    }
    GBAR(g);

    // ==== pretest: M - x > 0.05 (no good load; pos => pre since good < 1) ====
    float xx[2], M[2];
    bool  pre[2];
    #pragma unroll
    for (int k = 0; k < 2; k++) {
        int jj = 1 + ty + k * 8, ii = 1 + tx;
        float m = xs[g][jj - 1][ii - 1];
        m = fmaxf(m, xs[g][jj - 1][ii    ]);
        m = fmaxf(m, xs[g][jj - 1][ii + 1]);
        m = fmaxf(m, xs[g][jj    ][ii - 1]);
        m = fmaxf(m, xs[g][jj    ][ii    ]);
        m = fmaxf(m, xs[g][jj    ][ii + 1]);
        m = fmaxf(m, xs[g][jj + 1][ii - 1]);
        m = fmaxf(m, xs[g][jj + 1][ii    ]);
        m = fmaxf(m, xs[g][jj + 1][ii + 1]);
        M[k]  = m;
        xx[k] = xs[g][jj][ii];
        pre[k] = __fsub_rn(m, xx[k]) > 0.05f;
    }
    {
        unsigned bp = __ballot_sync(0xffffffffu, pre[0] || pre[1]);
        if (tx == 0 && bp) atomicOr(&s_red1[g], 1);
    }
    GBAR(g);
    const int anyPre = s_red1[g];

    float gd[2];
    bool  pos[2] = {false, false};
    if (anyPre) {
        // ==== exact pos test (loads good; coalesced) ====
        #pragma unroll
        for (int k = 0; k < 2; k++) {
            int jj = 1 + ty + k * 8, ii = 1 + tx;
            int r = r0 + jj - 1, c = c0 + ii - 1;
            gd[k] = good[r * WW + c];
            pos[k] = pre[k] &&
                     (__fsub_rn(__fmul_rn(M[k], gd[k]), xx[k]) > 0.05f);
            unsigned rowmask = __ballot_sync(0xffffffffu, pos[k]);
            if (tx == 0) s_rowpos[g][ty + k * 8] = rowmask;
        }
        unsigned bp = __ballot_sync(0xffffffffu, pos[0] || pos[1]);
        if (tx == 0 && bp) atomicOr(&s_red2[g], 1);
    }
    GBAR(g);
    const int any = s_red2[g];

    if (!any) {
        // no update possible -> refresh out buffer only if stale
        if (selfchg) {
            #pragma unroll
            for (int k = 0; k < 2; k++) {
                int jj = 1 + ty + k * 8, ii = 1 + tx;
                int r = r0 + jj - 1, c = c0 + ii - 1;
                xout[r * WW + c] = xx[k];
            }
        }
        if (gt == 0 && ((posw >> bx) & 1ull))
            atomicAnd(&g_posmask[by], ~(1ull << bx));
        return;                              // group-uniform exit
    }

    // ==== fill noised tile, cipher gated on pos-mask dilated 1 px ====
    #pragma unroll
    for (int k = 0; k < 3; k++) {
        int s = gt + k * 256;
        bool sv = s < NSLOT;
        int ss = sv ? s : 0;
        int j = ss / SW, ii = ss % SW;
        float x = sv ? xs[g][j][ii] : 0.0f;
        unsigned rm = 0;
        #pragma unroll
        for (int dr = 0; dr < 3; dr++) {
            int cr = j - 2 + dr;
            if (cr >= 0 && cr < TH) rm |= s_rowpos[g][cr];
        }
        ull rm2 = ((ull)rm) << 2;
        bool needc = (((rm2 >> ii) & 7ull) != 0ull) && (x > 0.0f);
        float y1 = 0.0f;
        if (__ballot_sync(0xffffffffu, needc)) {
            int r = r0 - 1 + j, c = c0 - 1 + ii;
            uint32_t p = (uint32_t)(min(max(r, 0), HH - 1) * WW +
                                    min(max(c, 0), WW - 1));
            float u = bits_to_uniform(pbits(k1a, k1b, p));
            float f = __fadd_rn(0.9999f, __fmul_rn(1e-4f, u));
            y1 = __fmul_rn(x, f);
        }
        if (sv) ys[g][j][ii] = y1;
    }
    GBAR(g);

    // ==== maxpool + coin (cipher gated on pos) + write ====
    int chg = 0;
    #pragma unroll
    for (int k = 0; k < 2; k++) {
        int jj = 1 + ty + k * 8, ii = 1 + tx;
        float m = ys[g][jj - 1][ii - 1];
        m = fmaxf(m, ys[g][jj - 1][ii    ]);
        m = fmaxf(m, ys[g][jj - 1][ii + 1]);
        m = fmaxf(m, ys[g][jj    ][ii - 1]);
        m = fmaxf(m, ys[g][jj    ][ii    ]);
        m = fmaxf(m, ys[g][jj    ][ii + 1]);
        m = fmaxf(m, ys[g][jj + 1][ii - 1]);
        m = fmaxf(m, ys[g][jj + 1][ii    ]);
        m = fmaxf(m, ys[g][jj + 1][ii + 1]);

        int r = r0 + jj - 1, c = c0 + ii - 1;
        uint32_t p = (uint32_t)(r * WW + c);
        float y4 = 0.0f;
        if (__ballot_sync(0xffffffffu, pos[k])) {
            uint32_t bits = pbits(k2a, k2b, p);
            bool coin = ((bits >> 9) > 0x400000u);   // u > 0.5 strictly
            if (coin && m > 0.0f) y4 = __fmul_rn(m, gd[k]);
        }
        float d  = __fsub_rn(y4, xx[k]);
        float y5 = (d > 0.05f) ? y4 : 0.0f;
        float out = fmaxf(y5, xx[k]);
        xout[p] = out;
        chg |= (out != xx[k]) ? 1 : 0;
    }
    {
        unsigned bc = __ballot_sync(0xffffffffu, chg != 0);
        if (tx == 0 && bc) atomicOr(&s_red3[g], 1);
    }
    GBAR(g);
    if (gt == 0) {
        ull bit = 1ull << bx;
        if (s_red3[g]) atomicOr(&g_chmask[cur][by], bit);
        if (!((posw >> bx) & 1ull)) atomicOr(&g_posmask[by], bit);
    }
}

// ---------------------------------------------------------------------------
// Host: per-iteration key schedule (fold_in + partitionable split), ping-pong
// data buffers, 3-parity changed masks. 101 launches total.
// ---------------------------------------------------------------------------
extern "C" void kernel_launch(void* const* d_in, const int* in_sizes, int n_in,
                              void* d_out, int out_size) {
    const float* seed = (const float*)d_in[0];
    const float* hab  = (const float*)d_in[1];
    const float* good = (const float*)d_in[2];
    float* xout = (float*)d_out;

    float* scratch = nullptr;
    cudaGetSymbolAddress((void**)&scratch, g_scratch);

    init_kernel<<<(NPIX / 4 + 255) / 256, 256>>>(seed, hab, good, xout);

    for (int i = 0; i < 100; i++) {
        // fold_in(key(42)=(0,42), i) = cipher((0,42), (0,i))
        uint32_t f0, f1;
        tf2x32(0u, 42u, 0u, (uint32_t)i, f0, f1);
        // partitionable split: k1 = cipher(f,(0,0)), k2 = cipher(f,(0,1))
        uint32_t k1a, k1b, k2a, k2b;
        tf2x32(f0, f1, 0u, 0u, k1a, k1b);
        tf2x32(f0, f1, 0u, 1u, k2a, k2b);

        const int cur = i % 3, prev = (i + 2) % 3, nxt = (i + 1) % 3;
        const float* xin = (i & 1) ? scratch : xout;
        float*       xo  = (i & 1) ? xout    : scratch;

        step_kernel<<<STEP_GRID, 1024>>>(xin, xo, good, k1a, k1b, k2a, k2b,
                                         prev, cur, nxt);
    }
    // i = 99 (odd) wrote into xout -> final state lands in d_out
}

// round 12
// speedup vs baseline: 1.4953x; 1.4953x over previous
#include <cuda_runtime.h>
#include <stdint.h>

#define HH 2048
#define WW 2048
#define NPIX (HH * WW)

#define TW 32                    // tile width
#define TH 16                    // tile height
#define SW (TW + 2)              // 34 (halo)
#define SH (TH + 2)              // 18 (halo)
#define NSLOT (SW * SH)          // 612

#define NBX 64                   // tiles per row (bits in a mask word)
#define NBY 128                  // tile rows
#define NB  (NBX * NBY)          // 8192

#define SWITCH_ITER 32           // iters < SWITCH: 1 tile/block; after: 4

typedef unsigned long long ull;

__device__ float g_scratch[NPIX];
__device__ ull g_chmask[3][NBY];   // changed bits, 3-parity rotation
__device__ ull g_posmask[NBY];     // possible bits

// ---------------------------------------------------------------------------
// Threefry-2x32, 20 rounds — exact transcription of jax._src.prng
// ---------------------------------------------------------------------------
__host__ __device__ __forceinline__ uint32_t rotl32(uint32_t v, uint32_t r) {
#ifdef __CUDA_ARCH__
    return __funnelshift_l(v, v, r);
#else
    return (v << r) | (v >> (32u - r));
#endif
}

__host__ __device__ __forceinline__ void tf2x32(uint32_t k0, uint32_t k1,
                                                uint32_t x0, uint32_t x1,
                                                uint32_t& o0, uint32_t& o1) {
    uint32_t ks2 = k0 ^ k1 ^ 0x1BD11BDAu;
    x0 += k0; x1 += k1;
#define TF_R(r) { x0 += x1; x1 = rotl32(x1, r); x1 ^= x0; }
    TF_R(13u) TF_R(15u) TF_R(26u) TF_R(6u)
    x0 += k1;  x1 += ks2 + 1u;
    TF_R(17u) TF_R(29u) TF_R(16u) TF_R(24u)
    x0 += ks2; x1 += k0 + 2u;
    TF_R(13u) TF_R(15u) TF_R(26u) TF_R(6u)
    x0 += k0;  x1 += k1 + 3u;
    TF_R(17u) TF_R(29u) TF_R(16u) TF_R(24u)
    x0 += k1;  x1 += ks2 + 4u;
    TF_R(13u) TF_R(15u) TF_R(26u) TF_R(6u)
    x0 += ks2; x1 += k0 + 5u;
#undef TF_R
    o0 = x0; o1 = x1;
}

// Partitionable-mode random bits for flat index p: counter=(0,p); bits=o0^o1
__device__ __forceinline__ uint32_t pbits(uint32_t k0, uint32_t k1, uint32_t p) {
    uint32_t o0, o1;
    tf2x32(k0, k1, 0u, p, o0, o1);
    return o0 ^ o1;
}

__device__ __forceinline__ float bits_to_uniform(uint32_t bits) {
    return __fsub_rn(__uint_as_float((bits >> 9) | 0x3f800000u), 1.0f);
}

// ---------------------------------------------------------------------------
// x0 = seed * habitat * goodness  (+ reset masks)
// ---------------------------------------------------------------------------
__global__ void init_kernel(const float* __restrict__ seed,
                            const float* __restrict__ hab,
                            const float* __restrict__ good,
                            float* __restrict__ xout) {
    int idx = blockIdx.x * blockDim.x + threadIdx.x;
    if (idx < NPIX / 4) {
        const float4 s = ((const float4*)seed)[idx];
        const float4 h = ((const float4*)hab)[idx];
        const float4 g = ((const float4*)good)[idx];
        float4 o;
        o.x = __fmul_rn(__fmul_rn(s.x, h.x), g.x);
        o.y = __fmul_rn(__fmul_rn(s.y, h.y), g.y);
        o.z = __fmul_rn(__fmul_rn(s.z, h.z), g.z);
        o.w = __fmul_rn(__fmul_rn(s.w, h.w), g.w);
        ((float4*)xout)[idx] = o;
    }
    if (idx < NBY) {
        g_chmask[2][idx] = ~0ull;   // prev parity of iter 0 -> force all tiles
        g_chmask[0][idx] = 0ull;
        g_chmask[1][idx] = 0ull;
        g_posmask[idx]   = 0ull;
    }
}

// ---------------------------------------------------------------------------
// One spread step, TPB adjacent tiles per block (templated).
//   y1 = x * (0.9999 + 1e-4*u1); y2 = maxpool3x3(y1); y3 = y2*(u2>0.5);
//   y4 = y3*goodness; x' = max(y4*((y4-x) > 0.05), x)
// Skip hierarchy (exact: good<1, noise factor <= 1):
//   tile masks -> pretest M-x>0.05 (no good load) -> exact pos -> gated RNG.
// ---------------------------------------------------------------------------
template <int TPB>
__global__ __launch_bounds__(256)
void step_kernel(const float* __restrict__ xin, float* __restrict__ xout,
                 const float* __restrict__ good,
                 uint32_t k1a, uint32_t k1b, uint32_t k2a, uint32_t k2b,
                 int prev, int cur, int nxt) {
    __shared__ float xs[SH][SW];     // raw x (tile + halo)
    __shared__ float ys[SH][SW];     // noised x (maxpool operand)
    __shared__ unsigned s_rowpos[TH];

    const int tid = threadIdx.x;
    const int tx = tid & 31;
    const int ty = tid >> 5;                     // 0..7

    // zero the next-parity mask row (not read or written this launch)
    if (blockIdx.x < NBY && tid == 0) g_chmask[nxt][blockIdx.x] = 0ull;

    const int tbase = blockIdx.x * TPB;
    const int by  = tbase >> 6;
    const int bx0 = tbase & 63;

    // uniform mask loads (LDG broadcast; shared by all TPB tiles)
    ull nbm = g_chmask[prev][by];
    const ull chm = nbm;
    if (by > 0)       nbm |= g_chmask[prev][by - 1];
    if (by < NBY - 1) nbm |= g_chmask[prev][by + 1];
    const ull posw = g_posmask[by];

    #pragma unroll
    for (int kt = 0; kt < TPB; kt++) {
        const int bx = bx0 + kt;
        const ull colm = (bx == 0) ? 3ull : (7ull << (bx - 1));
        const bool need = ((nbm & colm) != 0ull) || (((posw >> bx) & 1ull) != 0ull);
        if (!need) continue;                     // uniform across block

        const int selfchg = (int)((chm >> bx) & 1ull);
        const int c0 = bx * TW, r0 = by * TH;

        if (TPB > 1) __syncthreads();            // smem reuse barrier

        // ==== load tile: core via float4 (0-127), halo ring (128-255) ====
        if (tid < 128) {
            int row = tid >> 3, q = tid & 7;
            const float4 v = *(const float4*)&xin[(r0 + row) * WW + c0 + q * 4];
            float* dst = &xs[row + 1][1 + q * 4];
            dst[0] = v.x; dst[1] = v.y; dst[2] = v.z; dst[3] = v.w;
        } else {
            int h = tid - 128;
            if (h < 100) {
                int j, i;
                if (h < 34)      { j = 0;             i = h; }
                else if (h < 68) { j = SH - 1;        i = h - 34; }
                else if (h < 84) { j = 1 + (h - 68);  i = 0; }
                else             { j = 1 + (h - 84);  i = SW - 1; }
                int r = r0 - 1 + j, c = c0 - 1 + i;
                bool ok = (r >= 0) && (r < HH) && (c >= 0) && (c < WW);
                xs[j][i] = ok ? xin[r * WW + c] : 0.0f;
            }
        }
        __syncthreads();

        // ==== pretest: M - x > 0.05 (no good load; pos => pre, good < 1) ====
        float xx[2], M[2];
        bool  pre[2];
        #pragma unroll
        for (int k = 0; k < 2; k++) {
            int jj = 1 + ty + k * 8, ii = 1 + tx;
            float m = xs[jj - 1][ii - 1];
            m = fmaxf(m, xs[jj - 1][ii    ]);
            m = fmaxf(m, xs[jj - 1][ii + 1]);
            m = fmaxf(m, xs[jj    ][ii - 1]);
            m = fmaxf(m, xs[jj    ][ii    ]);
            m = fmaxf(m, xs[jj    ][ii + 1]);
            m = fmaxf(m, xs[jj + 1][ii - 1]);
            m = fmaxf(m, xs[jj + 1][ii    ]);
            m = fmaxf(m, xs[jj + 1][ii + 1]);
            M[k]  = m;
            xx[k] = xs[jj][ii];
            pre[k] = __fsub_rn(m, xx[k]) > 0.05f;
        }
        int anyPre = __syncthreads_or((pre[0] || pre[1]) ? 1 : 0);

        float gd[2];
        bool  pos[2] = {false, false};
        int   any = 0;
        if (anyPre) {
            // ==== exact pos test (loads good; coalesced) ====
            #pragma unroll
            for (int k = 0; k < 2; k++) {
                int jj = 1 + ty + k * 8, ii = 1 + tx;
                int r = r0 + jj - 1, c = c0 + ii - 1;
                gd[k] = good[r * WW + c];
                pos[k] = pre[k] &&
                         (__fsub_rn(__fmul_rn(M[k], gd[k]), xx[k]) > 0.05f);
                unsigned rowmask = __ballot_sync(0xffffffffu, pos[k]);
                if (tx == 0) s_rowpos[ty + k * 8] = rowmask;
            }
            any = __syncthreads_or((pos[0] || pos[1]) ? 1 : 0);
        }

        if (!any) {
            // no update possible -> refresh out buffer only if stale
            if (selfchg) {
                #pragma unroll
                for (int k = 0; k < 2; k++) {
                    int jj = 1 + ty + k * 8, ii = 1 + tx;
                    int r = r0 + jj - 1, c = c0 + ii - 1;
                    xout[r * WW + c] = xx[k];
                }
            }
            if (tid == 0 && ((posw >> bx) & 1ull))
                atomicAnd(&g_posmask[by], ~(1ull << bx));
            continue;
        }

        // ==== fill noised tile, cipher gated on pos-mask dilated 1 px ====
        #pragma unroll
        for (int k = 0; k < 3; k++) {
            int s = tid + k * 256;
            bool sv = s < NSLOT;
            int ss = sv ? s : 0;
            int j = ss / SW, ii = ss % SW;
            float x = sv ? xs[j][ii] : 0.0f;
            unsigned rm = 0;
            #pragma unroll
            for (int dr = 0; dr < 3; dr++) {
                int cr = j - 2 + dr;
                if (cr >= 0 && cr < TH) rm |= s_rowpos[cr];
            }
            ull rm2 = ((ull)rm) << 2;
            bool needc = (((rm2 >> ii) & 7ull) != 0ull) && (x > 0.0f);
            float y1 = 0.0f;
            if (__ballot_sync(0xffffffffu, needc)) {
                int r = r0 - 1 + j, c = c0 - 1 + ii;
                uint32_t p = (uint32_t)(min(max(r, 0), HH - 1) * WW +
                                        min(max(c, 0), WW - 1));
                float u = bits_to_uniform(pbits(k1a, k1b, p));
                float f = __fadd_rn(0.9999f, __fmul_rn(1e-4f, u));
                y1 = __fmul_rn(x, f);
            }
            if (sv) ys[j][ii] = y1;
        }
        __syncthreads();

        // ==== maxpool + coin (cipher gated on pos) + write ====
        int chg = 0;
        #pragma unroll
        for (int k = 0; k < 2; k++) {
            int jj = 1 + ty + k * 8, ii = 1 + tx;
            float m = ys[jj - 1][ii - 1];
            m = fmaxf(m, ys[jj - 1][ii    ]);
            m = fmaxf(m, ys[jj - 1][ii + 1]);
            m = fmaxf(m, ys[jj    ][ii - 1]);
            m = fmaxf(m, ys[jj    ][ii    ]);
            m = fmaxf(m, ys[jj    ][ii + 1]);
            m = fmaxf(m, ys[jj + 1][ii - 1]);
            m = fmaxf(m, ys[jj + 1][ii    ]);
            m = fmaxf(m, ys[jj + 1][ii + 1]);

            int r = r0 + jj - 1, c = c0 + ii - 1;
            uint32_t p = (uint32_t)(r * WW + c);
            float y4 = 0.0f;
            if (__ballot_sync(0xffffffffu, pos[k])) {
                uint32_t bits = pbits(k2a, k2b, p);
                bool coin = ((bits >> 9) > 0x400000u);   // u > 0.5 strictly
                if (coin && m > 0.0f) y4 = __fmul_rn(m, gd[k]);
            }
            float d  = __fsub_rn(y4, xx[k]);
            float y5 = (d > 0.05f) ? y4 : 0.0f;
            float out = fmaxf(y5, xx[k]);
            xout[p] = out;
            chg |= (out != xx[k]) ? 1 : 0;
        }
        int anychg = __syncthreads_or(chg);
        if (tid == 0) {
            ull bit = 1ull << bx;
            if (anychg) atomicOr(&g_chmask[cur][by], bit);
            if (!((posw >> bx) & 1ull)) atomicOr(&g_posmask[by], bit);
        }
    }
}

// ---------------------------------------------------------------------------
// Host: hybrid schedule — 1 tile/block while the front grows (fast actives),
// 4 tiles/block afterwards (fast quiet floor). Identical math either way.
// ---------------------------------------------------------------------------
extern "C" void kernel_launch(void* const* d_in, const int* in_sizes, int n_in,
                              void* d_out, int out_size) {
    const float* seed = (const float*)d_in[0];
    const float* hab  = (const float*)d_in[1];
    const float* good = (const float*)d_in[2];
    float* xout = (float*)d_out;

    float* scratch = nullptr;
    cudaGetSymbolAddress((void**)&scratch, g_scratch);

    init_kernel<<<(NPIX / 4 + 255) / 256, 256>>>(seed, hab, good, xout);

    for (int i = 0; i < 100; i++) {
        // fold_in(key(42)=(0,42), i) = cipher((0,42), (0,i))
        uint32_t f0, f1;
        tf2x32(0u, 42u, 0u, (uint32_t)i, f0, f1);
        // partitionable split: k1 = cipher(f,(0,0)), k2 = cipher(f,(0,1))
        uint32_t k1a, k1b, k2a, k2b;
        tf2x32(f0, f1, 0u, 0u, k1a, k1b);
        tf2x32(f0, f1, 0u, 1u, k2a, k2b);

        const int cur = i % 3, prev = (i + 2) % 3, nxt = (i + 1) % 3;
        const float* xin = (i & 1) ? scratch : xout;
        float*       xo  = (i & 1) ? xout    : scratch;

        if (i < SWITCH_ITER)
            step_kernel<1><<<NB, 256>>>(xin, xo, good, k1a, k1b, k2a, k2b,
                                        prev, cur, nxt);
        else
            step_kernel<4><<<NB / 4, 256>>>(xin, xo, good, k1a, k1b, k2a, k2b,
                                            prev, cur, nxt);
    }
    // i = 99 (odd) wrote into xout -> final state lands in d_out
}

// round 13
// speedup vs baseline: 1.5493x; 1.0361x over previous
#include <cuda_runtime.h>
#include <stdint.h>

#define HH 2048
#define WW 2048
#define NPIX (HH * WW)

#define TW 32                    // tile width
#define TH 16                    // tile height
#define SW (TW + 2)              // 34 (halo)
#define SH (TH + 2)              // 18 (halo)
#define NSLOT (SW * SH)          // 612

#define NBX 64                   // tiles per row (bits in a mask word)
#define NBY 128                  // tile rows
#define NB  (NBX * NBY)          // 8192

#define SWITCH_ITER 32           // iters < SWITCH: 1 tile/block; after: 4

typedef unsigned long long ull;

__device__ float g_scratch[NPIX];
__device__ ull g_chmask[3][NBY];   // changed bits, 3-parity rotation
__device__ ull g_posmask[NBY];     // possible bits

// ---------------------------------------------------------------------------
// Threefry-2x32, 20 rounds — exact transcription of jax._src.prng
// ---------------------------------------------------------------------------
__host__ __device__ __forceinline__ uint32_t rotl32(uint32_t v, uint32_t r) {
#ifdef __CUDA_ARCH__
    return __funnelshift_l(v, v, r);
#else
    return (v << r) | (v >> (32u - r));
#endif
}

__host__ __device__ __forceinline__ void tf2x32(uint32_t k0, uint32_t k1,
                                                uint32_t x0, uint32_t x1,
                                                uint32_t& o0, uint32_t& o1) {
    uint32_t ks2 = k0 ^ k1 ^ 0x1BD11BDAu;
    x0 += k0; x1 += k1;
#define TF_R(r) { x0 += x1; x1 = rotl32(x1, r); x1 ^= x0; }
    TF_R(13u) TF_R(15u) TF_R(26u) TF_R(6u)
    x0 += k1;  x1 += ks2 + 1u;
    TF_R(17u) TF_R(29u) TF_R(16u) TF_R(24u)
    x0 += ks2; x1 += k0 + 2u;
    TF_R(13u) TF_R(15u) TF_R(26u) TF_R(6u)
    x0 += k0;  x1 += k1 + 3u;
    TF_R(17u) TF_R(29u) TF_R(16u) TF_R(24u)
    x0 += k1;  x1 += ks2 + 4u;
    TF_R(13u) TF_R(15u) TF_R(26u) TF_R(6u)
    x0 += ks2; x1 += k0 + 5u;
#undef TF_R
    o0 = x0; o1 = x1;
}

// Partitionable-mode random bits for flat index p: counter=(0,p); bits=o0^o1
__device__ __forceinline__ uint32_t pbits(uint32_t k0, uint32_t k1, uint32_t p) {
    uint32_t o0, o1;
    tf2x32(k0, k1, 0u, p, o0, o1);
    return o0 ^ o1;
}

__device__ __forceinline__ float bits_to_uniform(uint32_t bits) {
    return __fsub_rn(__uint_as_float((bits >> 9) | 0x3f800000u), 1.0f);
}

// ---------------------------------------------------------------------------
// x0 = seed * habitat * goodness  (+ reset masks)
// ---------------------------------------------------------------------------
__global__ void init_kernel(const float* __restrict__ seed,
                            const float* __restrict__ hab,
                            const float* __restrict__ good,
                            float* __restrict__ xout) {
    int idx = blockIdx.x * blockDim.x + threadIdx.x;
    if (idx < NPIX / 4) {
        const float4 s = ((const float4*)seed)[idx];
        const float4 h = ((const float4*)hab)[idx];
        const float4 g = ((const float4*)good)[idx];
        float4 o;
        o.x = __fmul_rn(__fmul_rn(s.x, h.x), g.x);
        o.y = __fmul_rn(__fmul_rn(s.y, h.y), g.y);
        o.z = __fmul_rn(__fmul_rn(s.z, h.z), g.z);
        o.w = __fmul_rn(__fmul_rn(s.w, h.w), g.w);
        ((float4*)xout)[idx] = o;
    }
    if (idx < NBY) {
        g_chmask[2][idx] = ~0ull;   // prev parity of iter 0 -> force all tiles
        g_chmask[0][idx] = 0ull;
        g_chmask[1][idx] = 0ull;
        g_posmask[idx]   = 0ull;
    }
}

// ---------------------------------------------------------------------------
// One spread step, TPB adjacent tiles per block (templated).
//   y1 = x * (0.9999 + 1e-4*u1); y2 = maxpool3x3(y1); y3 = y2*(u2>0.5);
//   y4 = y3*goodness; x' = max(y4*((y4-x) > 0.05), x)
// PRETEST=1 (quiet phase): cheap M-x>0.05 test gates the good load.
// PRETEST=0 (growth phase): good loaded up-front in parallel with x tile
//   (one fewer barrier round; same pos values either way — good < 1).
// ---------------------------------------------------------------------------
template <int TPB, int PRETEST>
__global__ __launch_bounds__(256)
void step_kernel(const float* __restrict__ xin, float* __restrict__ xout,
                 const float* __restrict__ good,
                 uint32_t k1a, uint32_t k1b, uint32_t k2a, uint32_t k2b,
                 int prev, int cur, int nxt) {
    __shared__ float xs[SH][SW];     // raw x (tile + halo)
    __shared__ float ys[SH][SW];     // noised x (maxpool operand)
    __shared__ unsigned s_rowpos[TH];

    const int tid = threadIdx.x;
    const int tx = tid & 31;
    const int ty = tid >> 5;                     // 0..7

    // zero the next-parity mask row (not read or written this launch)
    if (blockIdx.x < NBY && tid == 0) g_chmask[nxt][blockIdx.x] = 0ull;

    const int tbase = blockIdx.x * TPB;
    const int by  = tbase >> 6;
    const int bx0 = tbase & 63;

    // uniform mask loads (LDG broadcast; shared by all TPB tiles)
    ull nbm = g_chmask[prev][by];
    const ull chm = nbm;
    if (by > 0)       nbm |= g_chmask[prev][by - 1];
    if (by < NBY - 1) nbm |= g_chmask[prev][by + 1];
    const ull posw = g_posmask[by];

    #pragma unroll
    for (int kt = 0; kt < TPB; kt++) {
        const int bx = bx0 + kt;
        const ull colm = (bx == 0) ? 3ull : (7ull << (bx - 1));
        const bool need = ((nbm & colm) != 0ull) || (((posw >> bx) & 1ull) != 0ull);
        if (!need) continue;                     // uniform across block

        const int selfchg = (int)((chm >> bx) & 1ull);
        const int c0 = bx * TW, r0 = by * TH;

        if (TPB > 1) __syncthreads();            // smem reuse barrier

        float gd[2];
        if (!PRETEST) {
            // growth phase: issue good loads first; overlap with x tile load
            #pragma unroll
            for (int k = 0; k < 2; k++)
                gd[k] = good[(r0 + ty + k * 8) * WW + c0 + tx];
        }

        // ==== load tile: core via float4 (0-127), halo ring (128-255) ====
        if (tid < 128) {
            int row = tid >> 3, q = tid & 7;
            const float4 v = *(const float4*)&xin[(r0 + row) * WW + c0 + q * 4];
            float* dst = &xs[row + 1][1 + q * 4];
            dst[0] = v.x; dst[1] = v.y; dst[2] = v.z; dst[3] = v.w;
        } else {
            int h = tid - 128;
            if (h < 100) {
                int j, i;
                if (h < 34)      { j = 0;             i = h; }
                else if (h < 68) { j = SH - 1;        i = h - 34; }
                else if (h < 84) { j = 1 + (h - 68);  i = 0; }
                else             { j = 1 + (h - 84);  i = SW - 1; }
                int r = r0 - 1 + j, c = c0 - 1 + i;
                bool ok = (r >= 0) && (r < HH) && (c >= 0) && (c < WW);
                xs[j][i] = ok ? xin[r * WW + c] : 0.0f;
            }
        }
        __syncthreads();

        // ==== maxpool over raw x ====
        float xx[2], M[2];
        #pragma unroll
        for (int k = 0; k < 2; k++) {
            int jj = 1 + ty + k * 8, ii = 1 + tx;
            float m = xs[jj - 1][ii - 1];
            m = fmaxf(m, xs[jj - 1][ii    ]);
            m = fmaxf(m, xs[jj - 1][ii + 1]);
            m = fmaxf(m, xs[jj    ][ii - 1]);
            m = fmaxf(m, xs[jj    ][ii    ]);
            m = fmaxf(m, xs[jj    ][ii + 1]);
            m = fmaxf(m, xs[jj + 1][ii - 1]);
            m = fmaxf(m, xs[jj + 1][ii    ]);
            m = fmaxf(m, xs[jj + 1][ii + 1]);
            M[k]  = m;
            xx[k] = xs[jj][ii];
        }

        bool pos[2] = {false, false};
        int  any = 0;
        if (PRETEST) {
            // quiet phase: gate the good load on the cheap upper bound
            bool pre[2];
            #pragma unroll
            for (int k = 0; k < 2; k++)
                pre[k] = __fsub_rn(M[k], xx[k]) > 0.05f;
            int anyPre = __syncthreads_or((pre[0] || pre[1]) ? 1 : 0);
            if (anyPre) {
                #pragma unroll
                for (int k = 0; k < 2; k++) {
                    gd[k] = good[(r0 + ty + k * 8) * WW + c0 + tx];
                    pos[k] = pre[k] &&
                             (__fsub_rn(__fmul_rn(M[k], gd[k]), xx[k]) > 0.05f);
                    unsigned rowmask = __ballot_sync(0xffffffffu, pos[k]);
                    if (tx == 0) s_rowpos[ty + k * 8] = rowmask;
                }
                any = __syncthreads_or((pos[0] || pos[1]) ? 1 : 0);
            }
        } else {
            // growth phase: good already in registers; single reduction
            #pragma unroll
            for (int k = 0; k < 2; k++) {
                pos[k] = __fsub_rn(__fmul_rn(M[k], gd[k]), xx[k]) > 0.05f;
                unsigned rowmask = __ballot_sync(0xffffffffu, pos[k]);
                if (tx == 0) s_rowpos[ty + k * 8] = rowmask;
            }
            any = __syncthreads_or((pos[0] || pos[1]) ? 1 : 0);
        }

        if (!any) {
            // no update possible -> refresh out buffer only if stale
            if (selfchg) {
                #pragma unroll
                for (int k = 0; k < 2; k++)
                    xout[(r0 + ty + k * 8) * WW + c0 + tx] = xx[k];
            }
            if (tid == 0 && ((posw >> bx) & 1ull))
                atomicAnd(&g_posmask[by], ~(1ull << bx));
            continue;
        }

        // ==== fill noised tile, cipher gated on pos-mask dilated 1 px ====
        #pragma unroll
        for (int k = 0; k < 3; k++) {
            int s = tid + k * 256;
            bool sv = s < NSLOT;
            int ss = sv ? s : 0;
            int j = ss / SW, ii = ss % SW;
            float x = sv ? xs[j][ii] : 0.0f;
            unsigned rm = 0;
            #pragma unroll
            for (int dr = 0; dr < 3; dr++) {
                int cr = j - 2 + dr;
                if (cr >= 0 && cr < TH) rm |= s_rowpos[cr];
            }
            ull rm2 = ((ull)rm) << 2;
            bool needc = (((rm2 >> ii) & 7ull) != 0ull) && (x > 0.0f);
            float y1 = 0.0f;
            if (__ballot_sync(0xffffffffu, needc)) {
                int r = r0 - 1 + j, c = c0 - 1 + ii;
                uint32_t p = (uint32_t)(min(max(r, 0), HH - 1) * WW +
                                        min(max(c, 0), WW - 1));
                float u = bits_to_uniform(pbits(k1a, k1b, p));
                float f = __fadd_rn(0.9999f, __fmul_rn(1e-4f, u));
                y1 = __fmul_rn(x, f);
            }
            if (sv) ys[j][ii] = y1;
        }
        __syncthreads();

        // ==== maxpool + coin (cipher gated on pos) + write ====
        int chg = 0;
        #pragma unroll
        for (int k = 0; k < 2; k++) {
            int jj = 1 + ty + k * 8, ii = 1 + tx;
            float m = ys[jj - 1][ii - 1];
            m = fmaxf(m, ys[jj - 1][ii    ]);
            m = fmaxf(m, ys[jj - 1][ii + 1]);
            m = fmaxf(m, ys[jj    ][ii - 1]);
            m = fmaxf(m, ys[jj    ][ii    ]);
            m = fmaxf(m, ys[jj    ][ii + 1]);
            m = fmaxf(m, ys[jj + 1][ii - 1]);
            m = fmaxf(m, ys[jj + 1][ii    ]);
            m = fmaxf(m, ys[jj + 1][ii + 1]);

            uint32_t p = (uint32_t)((r0 + ty + k * 8) * WW + c0 + tx);
            float y4 = 0.0f;
            if (__ballot_sync(0xffffffffu, pos[k])) {
                uint32_t bits = pbits(k2a, k2b, p);
                bool coin = ((bits >> 9) > 0x400000u);   // u > 0.5 strictly
                if (coin && m > 0.0f) y4 = __fmul_rn(m, gd[k]);
            }
            float d  = __fsub_rn(y4, xx[k]);
            float y5 = (d > 0.05f) ? y4 : 0.0f;
            float out = fmaxf(y5, xx[k]);
            xout[p] = out;
            chg |= (out != xx[k]) ? 1 : 0;
        }
        int anychg = __syncthreads_or(chg);
        if (tid == 0) {
            ull bit = 1ull << bx;
            if (anychg) atomicOr(&g_chmask[cur][by], bit);
            if (!((posw >> bx) & 1ull)) atomicOr(&g_posmask[by], bit);
        }
    }
}

// ---------------------------------------------------------------------------
// Host: hybrid schedule — growth kernel (1 tile/block, no pretest, fused
// good load) for iters < 32; quiet kernel (4 tiles/block, pretest) after.
// ---------------------------------------------------------------------------
extern "C" void kernel_launch(void* const* d_in, const int* in_sizes, int n_in,
                              void* d_out, int out_size) {
    const float* seed = (const float*)d_in[0];
    const float* hab  = (const float*)d_in[1];
    const float* good = (const float*)d_in[2];
    float* xout = (float*)d_out;

    float* scratch = nullptr;
    cudaGetSymbolAddress((void**)&scratch, g_scratch);

    init_kernel<<<(NPIX / 4 + 255) / 256, 256>>>(seed, hab, good, xout);

    for (int i = 0; i < 100; i++) {
        // fold_in(key(42)=(0,42), i) = cipher((0,42), (0,i))
        uint32_t f0, f1;
        tf2x32(0u, 42u, 0u, (uint32_t)i, f0, f1);
        // partitionable split: k1 = cipher(f,(0,0)), k2 = cipher(f,(0,1))
        uint32_t k1a, k1b, k2a, k2b;
        tf2x32(f0, f1, 0u, 0u, k1a, k1b);
        tf2x32(f0, f1, 0u, 1u, k2a, k2b);

        const int cur = i % 3, prev = (i + 2) % 3, nxt = (i + 1) % 3;
        const float* xin = (i & 1) ? scratch : xout;
        float*       xo  = (i & 1) ? xout    : scratch;

        if (i < SWITCH_ITER)
            step_kernel<1, 0><<<NB, 256>>>(xin, xo, good, k1a, k1b, k2a, k2b,
                                           prev, cur, nxt);
        else
            step_kernel<4, 1><<<NB / 4, 256>>>(xin, xo, good, k1a, k1b, k2a, k2b,
                                               prev, cur, nxt);
    }
    // i = 99 (odd) wrote into xout -> final state lands in d_out
}

// round 14
// speedup vs baseline: 1.5654x; 1.0104x over previous
#include <cuda_runtime.h>
#include <stdint.h>

#define HH 2048
#define WW 2048
#define NPIX (HH * WW)

#define TW 32                    // tile width
#define TH 16                    // tile height
#define SW (TW + 2)              // 34 (halo 1)
#define SH (TH + 2)              // 18
#define NSLOT (SW * SH)          // 612

#define SW2 (TW + 4)             // 36 (halo 2, fused kernel)
#define SH2 (TH + 4)             // 20
#define NSLOT2 (SW2 * SH2)       // 720
#define SWA (TW + 2)             // 34 (core+1 region)
#define SHA (TH + 2)             // 18
#define NSLOTA (SWA * SHA)       // 612

#define NBX 64                   // tiles per row (bits in a mask word)
#define NBY 128                  // tile rows
#define NB  (NBX * NBY)          // 8192

#define GROWTH_ITERS 26          // single-step growth kernel
#define FUSED_LAUNCHES 36        // 72 iters fused (26..97)
// tail: iters 98,99 single-step quiet

typedef unsigned long long ull;

__device__ float g_scratch[NPIX];
__device__ ull g_chmask[3][NBY];   // changed bits, 3-parity rotation (per launch)
__device__ ull g_posmask[NBY];     // possible bits

// ---------------------------------------------------------------------------
// Threefry-2x32, 20 rounds — exact transcription of jax._src.prng
// ---------------------------------------------------------------------------
__host__ __device__ __forceinline__ uint32_t rotl32(uint32_t v, uint32_t r) {
#ifdef __CUDA_ARCH__
    return __funnelshift_l(v, v, r);
#else
    return (v << r) | (v >> (32u - r));
#endif
}

__host__ __device__ __forceinline__ void tf2x32(uint32_t k0, uint32_t k1,
                                                uint32_t x0, uint32_t x1,
                                                uint32_t& o0, uint32_t& o1) {
    uint32_t ks2 = k0 ^ k1 ^ 0x1BD11BDAu;
    x0 += k0; x1 += k1;
#define TF_R(r) { x0 += x1; x1 = rotl32(x1, r); x1 ^= x0; }
    TF_R(13u) TF_R(15u) TF_R(26u) TF_R(6u)
    x0 += k1;  x1 += ks2 + 1u;
    TF_R(17u) TF_R(29u) TF_R(16u) TF_R(24u)
    x0 += ks2; x1 += k0 + 2u;
    TF_R(13u) TF_R(15u) TF_R(26u) TF_R(6u)
    x0 += k0;  x1 += k1 + 3u;
    TF_R(17u) TF_R(29u) TF_R(16u) TF_R(24u)
    x0 += k1;  x1 += ks2 + 4u;
    TF_R(13u) TF_R(15u) TF_R(26u) TF_R(6u)
    x0 += ks2; x1 += k0 + 5u;
#undef TF_R
    o0 = x0; o1 = x1;
}

// Partitionable-mode random bits for flat index p: counter=(0,p); bits=o0^o1
__device__ __forceinline__ uint32_t pbits(uint32_t k0, uint32_t k1, uint32_t p) {
    uint32_t o0, o1;
    tf2x32(k0, k1, 0u, p, o0, o1);
    return o0 ^ o1;
}

__device__ __forceinline__ float bits_to_uniform(uint32_t bits) {
    return __fsub_rn(__uint_as_float((bits >> 9) | 0x3f800000u), 1.0f);
}

#define MAX9(A, a, b, m) do {                                   \
    m = A[a][b];                                                \
    m = fmaxf(m, A[a][b + 1]);   m = fmaxf(m, A[a][b + 2]);     \
    m = fmaxf(m, A[a + 1][b]);   m = fmaxf(m, A[a + 1][b + 1]); \
    m = fmaxf(m, A[a + 1][b + 2]);                              \
    m = fmaxf(m, A[a + 2][b]);   m = fmaxf(m, A[a + 2][b + 1]); \
    m = fmaxf(m, A[a + 2][b + 2]); } while (0)

// ---------------------------------------------------------------------------
// x0 = seed * habitat * goodness  (+ reset masks)
// ---------------------------------------------------------------------------
__global__ void init_kernel(const float* __restrict__ seed,
                            const float* __restrict__ hab,
                            const float* __restrict__ good,
                            float* __restrict__ xout) {
    int idx = blockIdx.x * blockDim.x + threadIdx.x;
    if (idx < NPIX / 4) {
        const float4 s = ((const float4*)seed)[idx];
        const float4 h = ((const float4*)hab)[idx];
        const float4 g = ((const float4*)good)[idx];
        float4 o;
        o.x = __fmul_rn(__fmul_rn(s.x, h.x), g.x);
        o.y = __fmul_rn(__fmul_rn(s.y, h.y), g.y);
        o.z = __fmul_rn(__fmul_rn(s.z, h.z), g.z);
        o.w = __fmul_rn(__fmul_rn(s.w, h.w), g.w);
        ((float4*)xout)[idx] = o;
    }
    if (idx < NBY) {
        g_chmask[2][idx] = ~0ull;   // prev parity of launch 0 -> force all
        g_chmask[0][idx] = 0ull;
        g_chmask[1][idx] = 0ull;
        g_posmask[idx]   = 0ull;
    }
}

// ---------------------------------------------------------------------------
// Single spread step, TPB adjacent tiles per block (templated).
// PRETEST=1: cheap M-x>0.05 gate before the good load (quiet phase).
// PRETEST=0: good loaded up-front, overlapped with x tile load (growth).
// ---------------------------------------------------------------------------
template <int TPB, int PRETEST>
__global__ __launch_bounds__(256)
void step_kernel(const float* __restrict__ xin, float* __restrict__ xout,
                 const float* __restrict__ good,
                 uint32_t k1a, uint32_t k1b, uint32_t k2a, uint32_t k2b,
                 int prev, int cur, int nxt) {
    __shared__ float xs[SH][SW];
    __shared__ float ys[SH][SW];
    __shared__ unsigned s_rowpos[TH];

    const int tid = threadIdx.x;
    const int tx = tid & 31;
    const int ty = tid >> 5;

    if (blockIdx.x < NBY && tid == 0) g_chmask[nxt][blockIdx.x] = 0ull;

    const int tbase = blockIdx.x * TPB;
    const int by  = tbase >> 6;
    const int bx0 = tbase & 63;

    ull nbm = g_chmask[prev][by];
    const ull chm = nbm;
    if (by > 0)       nbm |= g_chmask[prev][by - 1];
    if (by < NBY - 1) nbm |= g_chmask[prev][by + 1];
    const ull posw = g_posmask[by];

    #pragma unroll
    for (int kt = 0; kt < TPB; kt++) {
        const int bx = bx0 + kt;
        const ull colm = (bx == 0) ? 3ull : (7ull << (bx - 1));
        const bool need = ((nbm & colm) != 0ull) || (((posw >> bx) & 1ull) != 0ull);
        if (!need) continue;

        const int selfchg = (int)((chm >> bx) & 1ull);
        const int c0 = bx * TW, r0 = by * TH;

        if (TPB > 1) __syncthreads();

        float gd[2];
        if (!PRETEST) {
            #pragma unroll
            for (int k = 0; k < 2; k++)
                gd[k] = good[(r0 + ty + k * 8) * WW + c0 + tx];
        }

        if (tid < 128) {
            int row = tid >> 3, q = tid & 7;
            const float4 v = *(const float4*)&xin[(r0 + row) * WW + c0 + q * 4];
            float* dst = &xs[row + 1][1 + q * 4];
            dst[0] = v.x; dst[1] = v.y; dst[2] = v.z; dst[3] = v.w;
        } else {
            int h = tid - 128;
            if (h < 100) {
                int j, i;
                if (h < 34)      { j = 0;             i = h; }
                else if (h < 68) { j = SH - 1;        i = h - 34; }
                else if (h < 84) { j = 1 + (h - 68);  i = 0; }
                else             { j = 1 + (h - 84);  i = SW - 1; }
                int r = r0 - 1 + j, c = c0 - 1 + i;
                bool ok = (r >= 0) && (r < HH) && (c >= 0) && (c < WW);
                xs[j][i] = ok ? xin[r * WW + c] : 0.0f;
            }
        }
        __syncthreads();

        float xx[2], M[2];
        #pragma unroll
        for (int k = 0; k < 2; k++) {
            int jj = 1 + ty + k * 8, ii = 1 + tx;
            float m;
            MAX9(xs, jj - 1, ii - 1, m);
            M[k]  = m;
            xx[k] = xs[jj][ii];
        }

        bool pos[2] = {false, false};
        int  any = 0;
        if (PRETEST) {
            bool pre[2];
            #pragma unroll
            for (int k = 0; k < 2; k++)
                pre[k] = __fsub_rn(M[k], xx[k]) > 0.05f;
            int anyPre = __syncthreads_or((pre[0] || pre[1]) ? 1 : 0);
            if (anyPre) {
                #pragma unroll
                for (int k = 0; k < 2; k++) {
                    gd[k] = good[(r0 + ty + k * 8) * WW + c0 + tx];
                    pos[k] = pre[k] &&
                             (__fsub_rn(__fmul_rn(M[k], gd[k]), xx[k]) > 0.05f);
                    unsigned rowmask = __ballot_sync(0xffffffffu, pos[k]);
                    if (tx == 0) s_rowpos[ty + k * 8] = rowmask;
                }
                any = __syncthreads_or((pos[0] || pos[1]) ? 1 : 0);
            }
        } else {
            #pragma unroll
            for (int k = 0; k < 2; k++) {
                pos[k] = __fsub_rn(__fmul_rn(M[k], gd[k]), xx[k]) > 0.05f;
                unsigned rowmask = __ballot_sync(0xffffffffu, pos[k]);
                if (tx == 0) s_rowpos[ty + k * 8] = rowmask;
            }
            any = __syncthreads_or((pos[0] || pos[1]) ? 1 : 0);
        }

        if (!any) {
            if (selfchg) {
                #pragma unroll
                for (int k = 0; k < 2; k++)
                    xout[(r0 + ty + k * 8) * WW + c0 + tx] = xx[k];
            }
            if (tid == 0 && ((posw >> bx) & 1ull))
                atomicAnd(&g_posmask[by], ~(1ull << bx));
            continue;
        }

        // noise pass; gate: pos dilated 1px AND x > 0.05 (exact: a window
        // whose max comes from a <=0.05 cell can never pass the threshold)
        #pragma unroll
        for (int k = 0; k < 3; k++) {
            int s = tid + k * 256;
            bool sv = s < NSLOT;
            int ss = sv ? s : 0;
            int j = ss / SW, ii = ss % SW;
            float x = sv ? xs[j][ii] : 0.0f;
            unsigned rm = 0;
            #pragma unroll
            for (int dr = 0; dr < 3; dr++) {
                int cr = j - 2 + dr;
                if (cr >= 0 && cr < TH) rm |= s_rowpos[cr];
            }
            ull rm2 = ((ull)rm) << 2;
            bool needc = (((rm2 >> ii) & 7ull) != 0ull) && (x > 0.05f);
            float y1 = 0.0f;
            if (__ballot_sync(0xffffffffu, needc)) {
                int r = r0 - 1 + j, c = c0 - 1 + ii;
                uint32_t p = (uint32_t)(min(max(r, 0), HH - 1) * WW +
                                        min(max(c, 0), WW - 1));
                float u = bits_to_uniform(pbits(k1a, k1b, p));
                float f = __fadd_rn(0.9999f, __fmul_rn(1e-4f, u));
                y1 = __fmul_rn(x, f);
            }
            if (sv) ys[j][ii] = y1;
        }
        __syncthreads();

        int chg = 0;
        #pragma unroll
        for (int k = 0; k < 2; k++) {
            int jj = 1 + ty + k * 8, ii = 1 + tx;
            float m;
            MAX9(ys, jj - 1, ii - 1, m);
            uint32_t p = (uint32_t)((r0 + ty + k * 8) * WW + c0 + tx);
            float y4 = 0.0f;
            if (__ballot_sync(0xffffffffu, pos[k])) {
                uint32_t bits = pbits(k2a, k2b, p);
                bool coin = ((bits >> 9) > 0x400000u);
                if (coin && m > 0.0f) y4 = __fmul_rn(m, gd[k]);
            }
            float d  = __fsub_rn(y4, xx[k]);
            float y5 = (d > 0.05f) ? y4 : 0.0f;
            float out = fmaxf(y5, xx[k]);
            xout[p] = out;
            chg |= (out != xx[k]) ? 1 : 0;
        }
        int anychg = __syncthreads_or(chg);
        if (tid == 0) {
            ull bit = 1ull << bx;
            if (anychg) atomicOr(&g_chmask[cur][by], bit);
            if (!((posw >> bx) & 1ull)) atomicOr(&g_posmask[by], bit);
        }
    }
}

// ---------------------------------------------------------------------------
// TWO fused iterations per launch (quiet phase). Halo-2 tile; iter A on
// core+1 (ring recomputed bit-identically to neighbors), iter B on core.
// SOUND wake: need = dilate1(changed) | dilate1(pos) — the pos dilation is
// required because a neighbor's razor cell may ignite at sub-iter A and
// influence this tile at sub-iter B (this was R8's divergence).
// ---------------------------------------------------------------------------
__global__ __launch_bounds__(256)
void fused_kernel(const float* __restrict__ xin, float* __restrict__ xout,
                  const float* __restrict__ good,
                  uint32_t kA1a, uint32_t kA1b, uint32_t kA2a, uint32_t kA2b,
                  uint32_t kB1a, uint32_t kB1b, uint32_t kB2a, uint32_t kB2b,
                  int prev, int cur, int nxt) {
    __shared__ float xs[SH2][SW2];
    __shared__ float ys[SH2][SW2];
    __shared__ float xa[SHA][SWA];
    __shared__ float gs[SHA][SWA];
    __shared__ ull s_posA[SHA];
    __shared__ unsigned s_rowposB[TH];

    const int tid = threadIdx.x;
    const int tx = tid & 31;
    const int ty = tid >> 5;

    if (blockIdx.x < NBY && tid == 0) g_chmask[nxt][blockIdx.x] = 0ull;

    const int tbase = blockIdx.x * 2;
    const int by  = tbase >> 6;
    const int bx0 = tbase & 63;

    // wake: dilate1(changed) | dilate1(pos), both over the 3 tile rows
    ull needw = 0ull;
    const ull chm = g_chmask[prev][by];
    {
        ull a = chm | g_posmask[by];
        needw |= a | (a << 1) | (a >> 1);
        if (by > 0) {
            ull b = g_chmask[prev][by - 1] | g_posmask[by - 1];
            needw |= b | (b << 1) | (b >> 1);
        }
        if (by < NBY - 1) {
            ull c = g_chmask[prev][by + 1] | g_posmask[by + 1];
            needw |= c | (c << 1) | (c >> 1);
        }
    }
    const ull posw = g_posmask[by];

    #pragma unroll
    for (int kt = 0; kt < 2; kt++) {
        const int bx = bx0 + kt;
        if (!((needw >> bx) & 1ull)) continue;   // uniform across block

        const int selfchg = (int)((chm >> bx) & 1ull);
        const int c0 = bx * TW, r0 = by * TH;

        __syncthreads();                         // smem reuse barrier

        // ==== load x tile + halo2; zero posA masks ====
        #pragma unroll
        for (int q = 0; q < 3; q++) {
            int s = tid + q * 256;
            if (s < NSLOT2) {
                int j = s / SW2, i = s % SW2;
                int r = r0 - 2 + j, c = c0 - 2 + i;
                bool ok = (r >= 0) && (r < HH) && (c >= 0) && (c < WW);
                xs[j][i] = ok ? xin[r * WW + c] : 0.0f;
            }
        }
        if (tid < SHA) s_posA[tid] = 0ull;
        __syncthreads();

        // ==== iter A pos pass over core+1 (also loads good) ====
        bool posAv[3]; float xxA[3], gsv[3];
        #pragma unroll
        for (int q = 0; q < 3; q++) {
            int s = tid + q * 256;
            bool sv = s < NSLOTA;
            posAv[q] = false; xxA[q] = 0.0f; gsv[q] = 0.0f;
            if (sv) {
                int a = s / SWA, b = s % SWA;
                int r = r0 - 1 + a, c = c0 - 1 + b;
                bool inim = (r >= 0) && (r < HH) && (c >= 0) && (c < WW);
                float g = inim ? good[r * WW + c] : 0.0f;
                gsv[q] = g; gs[a][b] = g;
                float x = xs[a + 1][b + 1];
                xxA[q] = x;
                float M; MAX9(xs, a, b, M);
                if (inim && (__fsub_rn(__fmul_rn(M, g), x) > 0.05f)) {
                    posAv[q] = true;
                    atomicOr(&s_posA[a], 1ull << b);
                }
            }
        }
        int anyA = __syncthreads_or((posAv[0] || posAv[1] || posAv[2]) ? 1 : 0);

        if (!anyA) {
            // A no-op on core+1, so B's pos (on unchanged state) also empty
            if (selfchg) {
                #pragma unroll
                for (int k = 0; k < 2; k++) {
                    int rr = ty + k * 8, cc = tx;
                    xout[(r0 + rr) * WW + (c0 + cc)] = xs[rr + 2][cc + 2];
                }
            }
            if (tid == 0 && ((posw >> bx) & 1ull))
                atomicAnd(&g_posmask[by], ~(1ull << bx));
            continue;
        }

        // ==== iter A noise over halo2 region (gated, posA dilated 1) ====
        #pragma unroll
        for (int q = 0; q < 3; q++) {
            int s = tid + q * 256;
            bool sv = s < NSLOT2;
            int j = sv ? s / SW2 : 0, i = sv ? s % SW2 : 0;
            float x = sv ? xs[j][i] : 0.0f;
            ull rm = 0ull;
            #pragma unroll
            for (int dr = 0; dr < 3; dr++) {
                int ar = j - 2 + dr;
                if (ar >= 0 && ar < SHA) rm |= s_posA[ar];
            }
            ull rm2 = rm << 2;
            bool needc = (((rm2 >> i) & 7ull) != 0ull) && (x > 0.05f);
            float y1 = 0.0f;
            if (__ballot_sync(0xffffffffu, needc)) {
                int r = r0 - 2 + j, c = c0 - 2 + i;
                uint32_t p = (uint32_t)(min(max(r, 0), HH - 1) * WW +
                                        min(max(c, 0), WW - 1));
                float u = bits_to_uniform(pbits(kA1a, kA1b, p));
                float f = __fadd_rn(0.9999f, __fmul_rn(1e-4f, u));
                y1 = __fmul_rn(x, f);
            }
            if (sv) ys[j][i] = y1;
        }
        __syncthreads();

        // ==== iter A update over core+1 -> xa ====
        #pragma unroll
        for (int q = 0; q < 3; q++) {
            int s = tid + q * 256;
            bool sv = s < NSLOTA;
            int a = sv ? s / SWA : 0, b = sv ? s % SWA : 0;
            float m; MAX9(ys, a, b, m);
            float y4 = 0.0f;
            if (__ballot_sync(0xffffffffu, posAv[q])) {
                int r = r0 - 1 + a, c = c0 - 1 + b;
                uint32_t p = (uint32_t)(min(max(r, 0), HH - 1) * WW +
                                        min(max(c, 0), WW - 1));
                uint32_t bits = pbits(kA2a, kA2b, p);
                bool coin = ((bits >> 9) > 0x400000u);
                if (coin && m > 0.0f) y4 = __fmul_rn(m, gsv[q]);
            }
            float d  = __fsub_rn(y4, xxA[q]);
            float y5 = (d > 0.05f) ? y4 : 0.0f;
            if (sv) xa[a][b] = fmaxf(y5, xxA[q]);
        }
        __syncthreads();

        // ==== iter B pos pass over core ====
        bool posB[2]; float xab[2], gdB[2];
        #pragma unroll
        for (int k = 0; k < 2; k++) {
            int rr = ty + k * 8, cc = tx;
            float M; MAX9(xa, rr, cc, M);
            xab[k] = xa[rr + 1][cc + 1];
            gdB[k] = gs[rr + 1][cc + 1];
            posB[k] = __fsub_rn(__fmul_rn(M, gdB[k]), xab[k]) > 0.05f;
            unsigned rowmask = __ballot_sync(0xffffffffu, posB[k]);
            if (tx == 0) s_rowposB[rr] = rowmask;
        }
        int anyB = __syncthreads_or((posB[0] || posB[1]) ? 1 : 0);

        if (!anyB) {
            // B no-op; final = xa core (final state has no possible cells)
            int chg = 0;
            #pragma unroll
            for (int k = 0; k < 2; k++) {
                int rr = ty + k * 8, cc = tx;
                float out = xab[k];
                xout[(r0 + rr) * WW + (c0 + cc)] = out;
                chg |= (out != xs[rr + 2][cc + 2]) ? 1 : 0;
            }
            int anychg = __syncthreads_or(chg);
            if (tid == 0) {
                if (anychg) atomicOr(&g_chmask[cur][by], 1ull << bx);
                if ((posw >> bx) & 1ull)
                    atomicAnd(&g_posmask[by], ~(1ull << bx));
            }
            continue;
        }

        // ==== iter B noise over core+1 (reads xa) ====
        #pragma unroll
        for (int q = 0; q < 3; q++) {
            int s = tid + q * 256;
            bool sv = s < NSLOTA;
            int a = sv ? s / SWA : 0, b = sv ? s % SWA : 0;
            float x = sv ? xa[a][b] : 0.0f;
            unsigned rm = 0;
            #pragma unroll
            for (int dr = 0; dr < 3; dr++) {
                int br = a - 2 + dr;
                if (br >= 0 && br < TH) rm |= s_rowposB[br];
            }
            ull rm2 = ((ull)rm) << 2;
            bool needc = (((rm2 >> b) & 7ull) != 0ull) && (x > 0.05f);
            float y1 = 0.0f;
            if (__ballot_sync(0xffffffffu, needc)) {
                int r = r0 - 1 + a, c = c0 - 1 + b;
                uint32_t p = (uint32_t)(min(max(r, 0), HH - 1) * WW +
                                        min(max(c, 0), WW - 1));
                float u = bits_to_uniform(pbits(kB1a, kB1b, p));
                float f = __fadd_rn(0.9999f, __fmul_rn(1e-4f, u));
                y1 = __fmul_rn(x, f);
            }
            if (sv) ys[a][b] = y1;
        }
        __syncthreads();

        // ==== iter B final over core + write ====
        int chg = 0;
        #pragma unroll
        for (int k = 0; k < 2; k++) {
            int rr = ty + k * 8, cc = tx;
            float m; MAX9(ys, rr, cc, m);
            uint32_t p = (uint32_t)((r0 + rr) * WW + (c0 + cc));
            float y4 = 0.0f;
            if (__ballot_sync(0xffffffffu, posB[k])) {
                uint32_t bits = pbits(kB2a, kB2b, p);
                bool coin = ((bits >> 9) > 0x400000u);
                if (coin && m > 0.0f) y4 = __fmul_rn(m, gdB[k]);
            }
            float d  = __fsub_rn(y4, xab[k]);
            float y5 = (d > 0.05f) ? y4 : 0.0f;
            float out = fmaxf(y5, xab[k]);
            xout[p] = out;
            chg |= (out != xs[rr + 2][cc + 2]) ? 1 : 0;
        }
        int anychg = __syncthreads_or(chg);
        if (tid == 0) {
            ull bit = 1ull << bx;
            if (anychg) atomicOr(&g_chmask[cur][by], bit);
            if (!((posw >> bx) & 1ull)) atomicOr(&g_posmask[by], bit);
        }
    }
}

// ---------------------------------------------------------------------------
// Host: growth singles (iters 0-25) + 36 fused launches (26-97) + 2 singles
// (98-99). 3-parity rotation indexed by LAUNCH. Final state lands in d_out.
// ---------------------------------------------------------------------------
static void iter_keys(int i, uint32_t* k) {
    uint32_t f0, f1;
    tf2x32(0u, 42u, 0u, (uint32_t)i, f0, f1);        // fold_in
    tf2x32(f0, f1, 0u, 0u, k[0], k[1]);              // split k1
    tf2x32(f0, f1, 0u, 1u, k[2], k[3]);              // split k2
}

extern "C" void kernel_launch(void* const* d_in, const int* in_sizes, int n_in,
                              void* d_out, int out_size) {
    const float* seed = (const float*)d_in[0];
    const float* hab  = (const float*)d_in[1];
    const float* good = (const float*)d_in[2];
    float* xout = (float*)d_out;

    float* scratch = nullptr;
    cudaGetSymbolAddress((void**)&scratch, g_scratch);

    init_kernel<<<(NPIX / 4 + 255) / 256, 256>>>(seed, hab, good, xout);

    const float* cura = xout;    // holds current state
    float*       alt  = scratch;
    int l = 0;                   // launch counter for mask parity

    for (int i = 0; i < GROWTH_ITERS; i++, l++) {
        uint32_t k[4];
        iter_keys(i, k);
        step_kernel<1, 0><<<NB, 256>>>(cura, alt, good, k[0], k[1], k[2], k[3],
                                       (l + 2) % 3, l % 3, (l + 1) % 3);
        const float* t = cura; cura = alt; alt = (float*)t;
    }

    for (int t = 0; t < FUSED_LAUNCHES; t++, l++) {
        uint32_t kA[4], kB[4];
        iter_keys(GROWTH_ITERS + 2 * t, kA);
        iter_keys(GROWTH_ITERS + 2 * t + 1, kB);
        fused_kernel<<<NB / 2, 256>>>(cura, alt, good,
                                      kA[0], kA[1], kA[2], kA[3],
                                      kB[0], kB[1], kB[2], kB[3],
                                      (l + 2) % 3, l % 3, (l + 1) % 3);
        const float* tt = cura; cura = alt; alt = (float*)tt;
    }

    for (int i = 98; i < 100; i++, l++) {
        uint32_t k[4];
        iter_keys(i, k);
        step_kernel<4, 1><<<NB / 4, 256>>>(cura, alt, good,
                                           k[0], k[1], k[2], k[3],
                                           (l + 2) % 3, l % 3, (l + 1) % 3);
        const float* t = cura; cura = alt; alt = (float*)t;
    }
    // swaps: 26 + 36 + 2 = 64 (even) -> final state is in xout == d_out
}